// round 11
// baseline (speedup 1.0000x reference)
#include <cuda_runtime.h>
#include <cuda_fp16.h>
#include <cuda_bf16.h>

__device__ __forceinline__ float tanh_(float x){ float y; asm("tanh.approx.f32 %0, %1;" : "=f"(y) : "f"(x)); return y; }
__device__ __forceinline__ float ex2_(float x) { float y; asm("ex2.approx.f32 %0, %1;" : "=f"(y) : "f"(x)); return y; }
__device__ __forceinline__ float lg2_(float x) { float y; asm("lg2.approx.f32 %0, %1;" : "=f"(y) : "f"(x)); return y; }
__device__ __forceinline__ float sig_(float x) { return __frcp_rn(1.0f + ex2_(-1.44269504f * x)); }
__device__ __forceinline__ __half2 h2tanh_(__half2 x) {
    unsigned u = *(unsigned*)&x, y;
    asm("tanh.approx.f16x2 %0, %1;" : "=r"(y) : "r"(u));
    return *(__half2*)&y;
}
__device__ __forceinline__ __half2 h2shfl_(__half2 v, int off) {
    unsigned u = *(unsigned*)&v;
    u = __shfl_xor_sync(0xffffffffu, u, off);
    return *(__half2*)&u;
}

// 32 blocks x 1024 threads, zero inter-block communication (R3/R6/R8 all proved
// any cross-CTA exchange costs more than it saves here). R7 structure with the
// sweep packed f16x2: pair (h, h+128) shares each HFMA2 chain step, tanh.f16x2,
// and HFMA2 accumulation -> MUFU instrs 40->24/warp, FMA stream ~halved.
__global__ void __launch_bounds__(1024, 1)
qlstm_all(const int*   __restrict__ x,    // (1024,128)
          const float* __restrict__ qw,   // (4,2,8)
          const float* __restrict__ Wo,   // (4,256,8)
          const float* __restrict__ bo,   // (4,256)
          const float* __restrict__ fcW,  // (2,256)
          const float* __restrict__ fcb,  // (2,)
          float*       __restrict__ out)  // (1024,2)
{
    const int tid  = threadIdx.x;
    const int lane = tid & 31;
    const int wrp  = tid >> 5;
    const int row  = blockIdx.x * 32 + wrp;      // this warp's batch row

    __shared__ float  jALF[128][4];              // (A_i, A_{i+128}, l_i, l_{i+128})
    __shared__ __half pf_h[256];                 // packed (f_i, f_{i+128})
    __shared__ __half pig_h[256];                // packed ig
    __shared__ __half pq0_h[256];                // packed oo*fcW0
    __shared__ __half pq1_h[256];                // packed oo*fcW1
    __shared__ float2 s_s[128];                  // s_t table

    // Mask slice: issue immediately.
    const int4 px = *(const int4*)(x + row * 128 + lane * 4);

    // ---- Param phase (identical math to R7): warps 0..7, one h per thread.
    //      All global loads issued first; zeta/zz via pure warp shuffles.
    if (tid < 256) {
        const int h = tid;
        float4 w0a = ((const float4*)(Wo + (0 * 256 + h) * 8))[0];
        float4 w0b = ((const float4*)(Wo + (0 * 256 + h) * 8))[1];
        float4 w1a = ((const float4*)(Wo + (1 * 256 + h) * 8))[0];
        float4 w1b = ((const float4*)(Wo + (1 * 256 + h) * 8))[1];
        float4 w2a = ((const float4*)(Wo + (2 * 256 + h) * 8))[0];
        float4 w2b = ((const float4*)(Wo + (2 * 256 + h) * 8))[1];
        float4 w3a = ((const float4*)(Wo + (3 * 256 + h) * 8))[0];
        float4 w3b = ((const float4*)(Wo + (3 * 256 + h) * 8))[1];
        float b0 = bo[0 * 256 + h], b1 = bo[1 * 256 + h];
        float b2 = bo[2 * 256 + h], b3 = bo[3 * 256 + h];
        float fc0 = fcW[h], fc1 = fcW[256 + h];

        // zeta[g][j] = -sin(qw[g,0,j]) (H->RX global phase; RZ drops out);
        // CNOT-ring products zz gathered via shuffles, overlapping the loads.
        const int g_ = lane >> 3, j_ = lane & 7;
        const float zeta = -__sinf(qw[g_ * 16 + j_]);
        const int base = lane & 24;              // g*8
        float zzv = 1.0f;
#pragma unroll
        for (int j2 = 0; j2 < 8; j2++) {
            float zj = __shfl_sync(0xffffffffu, zeta, base + j2);
            bool incl = (j_ == 0) ? (j2 >= 1) : (j2 <= j_);
            zzv = incl ? zzv * zj : zzv;
        }
        // pre[g] = bo + Wo[g,h,:] . zz[g,:]
        float pre0 = b0, pre1 = b1, pre2 = b2, pre3 = b3;
#pragma unroll
        for (int q = 0; q < 4; q++) {
            float z0 = __shfl_sync(0xffffffffu, zzv,  0 + q);
            float z4 = __shfl_sync(0xffffffffu, zzv,  4 + q);
            float z8 = __shfl_sync(0xffffffffu, zzv,  8 + q);
            float z12= __shfl_sync(0xffffffffu, zzv, 12 + q);
            float z16= __shfl_sync(0xffffffffu, zzv, 16 + q);
            float z20= __shfl_sync(0xffffffffu, zzv, 20 + q);
            float z24= __shfl_sync(0xffffffffu, zzv, 24 + q);
            float z28= __shfl_sync(0xffffffffu, zzv, 28 + q);
            const float* a;
            a = (const float*)&w0a; pre0 += a[q] * z0;
            a = (const float*)&w0b; pre0 += a[q] * z4;
            a = (const float*)&w1a; pre1 += a[q] * z8;
            a = (const float*)&w1b; pre1 += a[q] * z12;
            a = (const float*)&w2a; pre2 += a[q] * z16;
            a = (const float*)&w2b; pre2 += a[q] * z20;
            a = (const float*)&w3a; pre3 += a[q] * z24;
            a = (const float*)&w3b; pre3 += a[q] * z28;
        }

        const float e   = ex2_(-1.44269504f * pre0);
        const float ope = 1.0f + e;
        const float f_  = __frcp_rn(ope);            // sigmoid(pre0)
        const float lf2 = -lg2_(ope);                // log2(f)
        const float ig_ = sig_(pre1) * tanh_(pre2);
        const float oo_ = sig_(pre3);
        const float omf = __fdividef(e, ope);        // 1 - f
        const float A_  = ig_ * __frcp_rn(omf);      // c_inf

        // Interleaved-pair tables: slot i pairs (h=i, h=i+128).
        const int i  = h & 127;
        const int hi = h >> 7;                       // 0 -> .x half, 1 -> .y half
        jALF[i][hi]     = A_;
        jALF[i][2 + hi] = lf2;
        const int hslot = (i << 1) | hi;
        pf_h [hslot] = __float2half_rn(f_);
        pig_h[hslot] = __float2half_rn(ig_);
        pq0_h[hslot] = __float2half_rn(oo_ * fc0);
        pq1_h[hslot] = __float2half_rn(oo_ * fc1);
    }
    __syncthreads();

    // ---- Packed sweep: warp w owns t in [4w,4w+4); lane owns pair-slots
    //      {lane+32k}. fp32 closed-form jump c_{4w} = A(1-f^{4w}), then 4
    //      exact fp16x2 recursion steps, tanh.f16x2, HFMA2 accumulation.
    {
        const float n0 = (float)(4 * wrp);
        const __half2 hz = __floats2half2_rn(0.f, 0.f);
        __half2 a0[4] = {hz, hz, hz, hz};            // class 0, t..t+3
        __half2 a1[4] = {hz, hz, hz, hz};            // class 1
        const __half2* pf  = (const __half2*)pf_h;
        const __half2* pig = (const __half2*)pig_h;
        const __half2* pq0 = (const __half2*)pq0_h;
        const __half2* pq1 = (const __half2*)pq1_h;
#pragma unroll
        for (int k = 0; k < 4; k++) {
            const int i = lane + 32 * k;
            const float4 J  = ((const float4*)jALF)[i];   // (A0, A1, l0, l1)
            const __half2 fh  = pf[i];
            const __half2 igh = pig[i];
            const __half2 q0h = pq0[i];
            const __half2 q1h = pq1[i];
            float fn0 = ex2_(n0 * J.z), fn1 = ex2_(n0 * J.w);
            __half2 ch = __floats2half2_rn(J.x - J.x * fn0, J.y - J.y * fn1);
#pragma unroll
            for (int t = 0; t < 4; t++) {
                ch = __hfma2(fh, ch, igh);
                __half2 th = h2tanh_(ch);
                a0[t] = __hfma2(q0h, th, a0[t]);
                a1[t] = __hfma2(q1h, th, a1[t]);
            }
        }
        // Butterfly h-reduction across lanes (packed adds)
#pragma unroll
        for (int off = 16; off; off >>= 1) {
#pragma unroll
            for (int t = 0; t < 4; t++) {
                a0[t] = __hadd2(a0[t], h2shfl_(a0[t], off));
                a1[t] = __hadd2(a1[t], h2shfl_(a1[t], off));
            }
        }
        if (lane == 0) {
#pragma unroll
            for (int t = 0; t < 4; t++) {
                float s0 = __low2float(a0[t]) + __high2float(a0[t]);
                float s1 = __low2float(a1[t]) + __high2float(a1[t]);
                s_s[4 * wrp + t] = make_float2(s0, s1);
            }
        }
    }
    __syncthreads();

    // ---- Stage 2: masks (in regs since start) x s table (vectorized LDS).
    const float4* st = (const float4*)s_s;
    float4 sa = st[lane * 2 + 0];
    float4 sb = st[lane * 2 + 1];
    float a0 = 0.0f, a1 = 0.0f, cnt = 0.0f, m;
    m = (px.x != 0) ? 1.0f : 0.0f; a0 += m * sa.x; a1 += m * sa.y; cnt += m;
    m = (px.y != 0) ? 1.0f : 0.0f; a0 += m * sa.z; a1 += m * sa.w; cnt += m;
    m = (px.z != 0) ? 1.0f : 0.0f; a0 += m * sb.x; a1 += m * sb.y; cnt += m;
    m = (px.w != 0) ? 1.0f : 0.0f; a0 += m * sb.z; a1 += m * sb.w; cnt += m;
#pragma unroll
    for (int off = 16; off; off >>= 1) {
        a0  += __shfl_xor_sync(0xffffffffu, a0, off);
        a1  += __shfl_xor_sync(0xffffffffu, a1, off);
        cnt += __shfl_xor_sync(0xffffffffu, cnt, off);
    }
    if (lane == 0) {
        float inv = __frcp_rn(cnt + 1e-9f);
        float2 o = make_float2(a0 * inv + fcb[0], a1 * inv + fcb[1]);
        *(float2*)(out + row * 2) = o;
    }
}

extern "C" void kernel_launch(void* const* d_in, const int* in_sizes, int n_in,
                              void* d_out, int out_size)
{
    // metadata order: x, embed, Wi, bi, qw, Wo, bo, fcW, fcb
    const int*   x   = (const int*)  d_in[0];
    const float* qw  = (const float*)d_in[4];
    const float* Wo  = (const float*)d_in[5];
    const float* bo  = (const float*)d_in[6];
    const float* fcW = (const float*)d_in[7];
    const float* fcb = (const float*)d_in[8];
    float* out = (float*)d_out;

    qlstm_all<<<32, 1024>>>(x, qw, Wo, bo, fcW, fcb, out);

    (void)in_sizes; (void)n_in; (void)out_size;
}